// round 11
// baseline (speedup 1.0000x reference)
#include <cuda_runtime.h>
#include <math.h>
#include <stdint.h>

#define TOK    4096
#define DMODEL 768
#define LDX    769
#define NHEAD  12
#define HD     64
#define SEQ    1024
#define NBH    48
#define MLP    3072

// ---------------- scratch (device globals; no allocation allowed) ----------
__device__ float g_h0[TOK * LDX];
__device__ float g_Sq[TOK * DMODEL];
__device__ float g_Sk[TOK * DMODEL];
__device__ float g_Sv[TOK * DMODEL];
__device__ float g_vt[TOK * DMODEL];
__device__ float g_qt[NBH * SEQ];
__device__ float g_kt[NBH * SEQ];
__device__ float g_attncat[TOK * LDX];
__device__ float g_attnt[TOK * NHEAD];
__device__ float g_res[TOK * DMODEL];
__device__ float g_h2[TOK * LDX];
__device__ float g_h3[TOK * (MLP + 1)];
__device__ float g_Sm[TOK * MLP];

// ---------------- helpers --------------------------------------------------
__device__ __forceinline__ float softplusf(float x) {
    return x > 20.f ? x : log1pf(__expf(x));
}

__device__ __forceinline__ uint32_t f2tf32(float v) {
    uint32_t u;
    asm("cvt.rna.tf32.f32 %0, %1;" : "=r"(u) : "f"(v));
    return u;
}

__device__ __forceinline__ unsigned long long fma_f32x2(
    unsigned long long a, unsigned long long b, unsigned long long c) {
    unsigned long long d;
    asm("fma.rn.f32x2 %0, %1, %2, %3;" : "=l"(d) : "l"(a), "l"(b), "l"(c));
    return d;
}
__device__ __forceinline__ unsigned long long pack_f32x2(float lo, float hi) {
    unsigned long long r;
    asm("mov.b64 %0, {%1, %2};" : "=l"(r) : "f"(lo), "f"(hi));
    return r;
}
__device__ __forceinline__ void unpack_f32x2(unsigned long long v, float& lo, float& hi) {
    asm("mov.b64 {%0, %1}, %2;" : "=f"(lo), "=f"(hi) : "l"(v));
}

__device__ __forceinline__ float block_sum(float v, float* red) {
#pragma unroll
    for (int o = 16; o > 0; o >>= 1) v += __shfl_xor_sync(0xffffffffu, v, o);
    int w = threadIdx.x >> 5;
    int nw = blockDim.x >> 5;
    if ((threadIdx.x & 31) == 0) red[w] = v;
    __syncthreads();
    float r = 0.f;
    for (int i = 0; i < nw; i++) r += red[i];
    __syncthreads();
    return r;
}

// ---------------- LayerNorm over 768 spatial dims, write [t, s] (769) ------
__global__ __launch_bounds__(256) void ln_rows_kernel(
    const float* __restrict__ in, int ld, int off,
    const float* __restrict__ gam, const float* __restrict__ bet,
    float* __restrict__ out)
{
    int row = blockIdx.x;
    const float* xr = in + row * ld + off;
    __shared__ float red[8];
    float v[3];
    float s1 = 0.f, s2 = 0.f;
#pragma unroll
    for (int r = 0; r < 3; r++) {
        int c = threadIdx.x + r * 256;
        float x = xr[c];
        v[r] = x; s1 += x; s2 += x * x;
    }
    s1 = block_sum(s1, red);
    s2 = block_sum(s2, red);
    float mu = s1 * (1.f / DMODEL);
    float var = s2 * (1.f / DMODEL) - mu * mu;
    float rstd = rsqrtf(var + 1e-5f);
    float ss = 0.f;
#pragma unroll
    for (int r = 0; r < 3; r++) {
        int c = threadIdx.x + r * 256;
        float nv = (v[r] - mu) * rstd * gam[c] + bet[c];
        out[row * LDX + 1 + c] = nv;
        ss += nv * nv;
    }
    ss = block_sum(ss, red);
    if (threadIdx.x == 0) out[row * LDX] = sqrtf(1.f + ss);
}

// ---------------- tf32 tensor-core GEMM (double-buffered) ------------------
#define BM 128
#define BN 128
#define BK 32
#define SKP 36
#define TILEU (BM * SKP)

__device__ __forceinline__ void gemm_body(
    const float* __restrict__ A, const float* __restrict__ B,
    float* __restrict__ C, int K, int lda, int ldb, int ldc,
    uint32_t* As, uint32_t* Bs, int m0, int n0)
{
    int tid  = threadIdx.x;
    int lane = tid & 31;
    int warp = tid >> 5;
    int warp_m = (warp >> 1) * 32;
    int warp_n = (warp & 1) * 64;
    int frow = lane >> 2;
    int fk   = lane & 3;
    int lm = tid >> 5;
    int lk = tid & 31;

    float acc[2][8][4];
#pragma unroll
    for (int i = 0; i < 2; i++)
#pragma unroll
        for (int j = 0; j < 8; j++)
#pragma unroll
            for (int c = 0; c < 4; c++) acc[i][j][c] = 0.f;

    int nT = (K + BK - 1) / BK;
    float aReg[16], bReg[16];

#pragma unroll
    for (int it = 0; it < 16; it++) {
        int m = lm + it * 8;
        aReg[it] = (lk < K) ? A[(m0 + m) * lda + lk] : 0.f;
        bReg[it] = (lk < K) ? B[(n0 + m) * ldb + lk] : 0.f;
    }
#pragma unroll
    for (int it = 0; it < 16; it++) {
        int m = lm + it * 8;
        As[m * SKP + lk] = f2tf32(aReg[it]);
        Bs[m * SKP + lk] = f2tf32(bReg[it]);
    }
    __syncthreads();

    for (int t = 0; t < nT; t++) {
        uint32_t* Ab = As + (t & 1) * TILEU;
        uint32_t* Bb = Bs + (t & 1) * TILEU;

        if (t + 1 < nT) {
            int k0 = (t + 1) * BK;
#pragma unroll
            for (int it = 0; it < 16; it++) {
                int m = lm + it * 8;
                int kk = k0 + lk;
                aReg[it] = (kk < K) ? A[(m0 + m) * lda + kk] : 0.f;
                bReg[it] = (kk < K) ? B[(n0 + m) * ldb + kk] : 0.f;
            }
        }

#pragma unroll
        for (int ks = 0; ks < 4; ks++) {
            int kb = ks * 8 + fk;
            uint32_t a[2][4];
#pragma unroll
            for (int i = 0; i < 2; i++) {
                int mr = warp_m + i * 16 + frow;
                a[i][0] = Ab[mr * SKP + kb];
                a[i][1] = Ab[(mr + 8) * SKP + kb];
                a[i][2] = Ab[mr * SKP + kb + 4];
                a[i][3] = Ab[(mr + 8) * SKP + kb + 4];
            }
#pragma unroll
            for (int j = 0; j < 8; j++) {
                int nr = warp_n + j * 8 + frow;
                uint32_t b0 = Bb[nr * SKP + kb];
                uint32_t b1 = Bb[nr * SKP + kb + 4];
#pragma unroll
                for (int i = 0; i < 2; i++) {
                    asm volatile(
                        "mma.sync.aligned.m16n8k8.row.col.f32.tf32.tf32.f32 "
                        "{%0,%1,%2,%3}, {%4,%5,%6,%7}, {%8,%9}, {%0,%1,%2,%3};"
                        : "+f"(acc[i][j][0]), "+f"(acc[i][j][1]),
                          "+f"(acc[i][j][2]), "+f"(acc[i][j][3])
                        : "r"(a[i][0]), "r"(a[i][1]), "r"(a[i][2]), "r"(a[i][3]),
                          "r"(b0), "r"(b1));
                }
            }
        }

        if (t + 1 < nT) {
            uint32_t* An = As + ((t + 1) & 1) * TILEU;
            uint32_t* Bn = Bs + ((t + 1) & 1) * TILEU;
#pragma unroll
            for (int it = 0; it < 16; it++) {
                int m = lm + it * 8;
                An[m * SKP + lk] = f2tf32(aReg[it]);
                Bn[m * SKP + lk] = f2tf32(bReg[it]);
            }
            __syncthreads();
        }
    }

#pragma unroll
    for (int i = 0; i < 2; i++) {
#pragma unroll
        for (int j = 0; j < 8; j++) {
            int row = m0 + warp_m + i * 16 + frow;
            int col = n0 + warp_n + j * 8 + fk * 2;
            C[row * ldc + col]           = acc[i][j][0];
            C[row * ldc + col + 1]       = acc[i][j][1];
            C[(row + 8) * ldc + col]     = acc[i][j][2];
            C[(row + 8) * ldc + col + 1] = acc[i][j][3];
        }
    }
}

__global__ __launch_bounds__(256, 2) void gemm_tf32_kernel(
    const float* __restrict__ A, const float* __restrict__ B,
    float* __restrict__ C, int K, int lda, int ldb, int ldc)
{
    extern __shared__ uint32_t smemU[];
    gemm_body(A, B, C, K, lda, ldb, ldc,
              smemU, smemU + 2 * TILEU, blockIdx.y * BM, blockIdx.x * BN);
}

__global__ __launch_bounds__(256, 2) void gemm_tf32_qkv_kernel(
    const float* __restrict__ A,
    const float* __restrict__ Wq, const float* __restrict__ Wk, const float* __restrict__ Wv,
    float* __restrict__ Sq, float* __restrict__ Sk, float* __restrict__ Sv)
{
    extern __shared__ uint32_t smemU[];
    const float* B = (blockIdx.z == 0) ? Wq : (blockIdx.z == 1) ? Wk : Wv;
    float* C       = (blockIdx.z == 0) ? Sq : (blockIdx.z == 1) ? Sk : Sv;
    gemm_body(A, B, C, LDX, LDX, LDX, DMODEL,
              smemU, smemU + 2 * TILEU, blockIdx.y * BM, blockIdx.x * BN);
}

// ---------------- QKV epilogue: q_t, k_t, v_tan ----------------------------
__global__ __launch_bounds__(64) void qkv_post_kernel() {
    int gid = blockIdx.x;             // bh*SEQ + i
    int bh = gid >> 10, i = gid & 1023;
    int b = bh / NHEAD, h = bh % NHEAD;
    int off = (b * SEQ + i) * DMODEL + h * HD + threadIdx.x;
    float q = g_Sq[off], k = g_Sk[off], vv = g_Sv[off];
    float sq = q * q, sk = k * k, sv = vv * vv;
#pragma unroll
    for (int o = 16; o > 0; o >>= 1) {
        sq += __shfl_xor_sync(0xffffffffu, sq, o);
        sk += __shfl_xor_sync(0xffffffffu, sk, o);
        sv += __shfl_xor_sync(0xffffffffu, sv, o);
    }
    __shared__ float red[6];
    if ((threadIdx.x & 31) == 0) {
        int w = threadIdx.x >> 5;
        red[w * 3 + 0] = sq; red[w * 3 + 1] = sk; red[w * 3 + 2] = sv;
    }
    __syncthreads();
    float Sq2 = red[0] + red[3], Sk2 = red[1] + red[4], Sv2 = red[2] + red[5];
    if (threadIdx.x == 0) {
        g_qt[gid] = sqrtf(1.f + Sq2);
        g_kt[gid] = sqrtf(1.f + Sk2);
    }
    float vt_time = sqrtf(1.f + Sv2);
    float sn = sqrtf(Sv2);
    float dist = acoshf(fmaxf(vt_time, 1.f + 1e-7f));
    g_vt[off] = vv * (dist / fmaxf(sn, 1e-8f));
}

// ---------------- attention v3: one query per thread, fixed-ref softmax ----
// All logits are provably < 0 (lp <= 0, tau*ent > 0), so exp(l) w.r.t. fixed
// reference 0 cannot overflow and terms >= ~1.5e-3 -- no running max needed.
// Removes the loop-carried (m,S) dependency entirely: every j independent.
// dyn smem floats: kc[128*64] | vc[128*64] | ktc[128]
#define CHK 128
__global__ __launch_bounds__(128, 3) void attn_kernel(
    const float* __restrict__ alpha_p, const float* __restrict__ tau_p,
    const float* __restrict__ lam_p)
{
    extern __shared__ float smdyn[];
    float* kc  = smdyn;
    float* vc  = smdyn + CHK * 64;
    float* ktc = smdyn + 2 * CHK * 64;

    int tid = threadIdx.x;
    int bh = blockIdx.y;
    int b = bh / NHEAD, h = bh % NHEAD;
    int i = blockIdx.x * 128 + tid;
    int tokbase = b * SEQ;

    float tau = softplusf(tau_p[0]);
    float lam = softplusf(lam_p[0]);
    float alpha = softplusf(alpha_p[0]);

    const float* qrow = g_Sq + (tokbase + i) * DMODEL + h * HD;
    unsigned long long q2[32];
#pragma unroll
    for (int dd = 0; dd < 32; dd++)
        q2[dd] = *reinterpret_cast<const unsigned long long*>(qrow + 2 * dd);

    float qt = g_qt[bh * SEQ + i];
    float coshOQ = fmaxf(qt, 1.f + 1e-7f);
    float c_t = fminf(acoshf(coshOQ), 40.f);
    float isOQ = 1.f / sinhf(c_t);
    float Bv = alpha * c_t / (1.f + alpha * c_t);

    float S = 0.f;
    unsigned long long acc2[32];
#pragma unroll
    for (int dd = 0; dd < 32; dd++) acc2[dd] = 0ull;

    for (int jc = 0; jc < SEQ; jc += CHK) {
        __syncthreads();
        for (int idx = tid; idx < CHK * 16; idx += 128) {
            int row = idx >> 4, c4 = idx & 15;
            const float* src = g_Sk + (tokbase + jc + row) * DMODEL + h * HD + c4 * 4;
            *reinterpret_cast<float4*>(kc + row * 64 + c4 * 4) =
                *reinterpret_cast<const float4*>(src);
            const float* srcv = g_vt + (tokbase + jc + row) * DMODEL + h * HD + c4 * 4;
            *reinterpret_cast<float4*>(vc + row * 64 + c4 * 4) =
                *reinterpret_cast<const float4*>(srcv);
        }
        if (tid < CHK) ktc[tid] = g_kt[bh * SEQ + jc + tid];
        __syncthreads();

#pragma unroll 2
        for (int j = 0; j < CHK; j++) {
            const ulonglong2* kr = reinterpret_cast<const ulonglong2*>(kc + j * 64);
            unsigned long long d2 = 0ull;
#pragma unroll
            for (int dd = 0; dd < 16; dd++) {
                ulonglong2 kk = kr[dd];
                d2 = fma_f32x2(q2[2 * dd],     kk.x, d2);
                d2 = fma_f32x2(q2[2 * dd + 1], kk.y, d2);
            }
            float dlo, dhi; unpack_f32x2(d2, dlo, dhi);
            float dot = dlo + dhi;

            float kt = ktc[j];
            float coshOK = fmaxf(kt, 1.f + 1e-7f);
            float raw_cosh = fmaxf(qt * kt - dot, 1.f);
            bool is_self = raw_cosh < 1.f + 1e-5f;
            float safe_cosh = is_self ? 2.f : raw_cosh;
            float t2 = safe_cosh * safe_cosh - 1.f;
            float invs = rsqrtf(t2);
            float sh = t2 * invs;
            float dist = __logf(safe_cosh + sh);
            float rawZ = (raw_cosh * coshOQ - coshOK) * isOQ * invs;
            float Z = is_self ? 1.f : fminf(fmaxf(rawZ, -1.f), 1.f);
            float dL = fminf(dist, 40.f);
            float lp = -lam * __logf(1.f + dL * dL);
            float xe = Bv + Z - 0.1f;
            float ent = __logf(1.f + __expf(xe));
            float l = lp - tau * ent;          // provably < 0

            float e = __expf(l);
            S += e;
            unsigned long long e2 = pack_f32x2(e, e);
            const ulonglong2* vr = reinterpret_cast<const ulonglong2*>(vc + j * 64);
#pragma unroll
            for (int dd = 0; dd < 16; dd++) {
                ulonglong2 vv = vr[dd];
                acc2[2 * dd]     = fma_f32x2(vv.x, e2, acc2[2 * dd]);
                acc2[2 * dd + 1] = fma_f32x2(vv.y, e2, acc2[2 * dd + 1]);
            }
        }
    }

    // epilogue: normalize, expmap0, write (all thread-local)
    float inv = 1.f / S;
    float a[64];
    float n2 = 0.f;
#pragma unroll
    for (int dd = 0; dd < 32; dd++) {
        float lo, hi; unpack_f32x2(acc2[dd], lo, hi);
        lo *= inv; hi *= inv;
        a[2 * dd] = lo; a[2 * dd + 1] = hi;
        n2 += lo * lo + hi * hi;
    }
    float nn = sqrtf(n2);
    float tt = coshf(nn);
    float sf = sinhf(nn) / fmaxf(nn, 1e-8f);
    float* orow = g_attncat + (tokbase + i) * LDX + 1 + h * HD;
#pragma unroll
    for (int d = 0; d < 64; d++) orow[d] = a[d] * sf;
    g_attnt[(tokbase + i) * NHEAD + h] = tt;
}

// ---------------- t_new = sqrt(sum_h t_h^2 - 11) ---------------------------
__global__ void attn_time_kernel() {
    int t = blockIdx.x * 256 + threadIdx.x;
    if (t < TOK) {
        float s = 0.f;
#pragma unroll
        for (int hh = 0; hh < NHEAD; hh++) { float a = g_attnt[t * NHEAD + hh]; s += a * a; }
        g_attncat[t * LDX] = sqrtf(s - (float)(NHEAD - 1));
    }
}

// ---------------- residual: res = So + x_s ---------------------------------
__global__ void resid_kernel(const float* __restrict__ x) {
    int idx = blockIdx.x * 256 + threadIdx.x;
    if (idx < TOK * DMODEL) {
        int row = idx / DMODEL, c = idx % DMODEL;
        g_res[idx] = g_Sq[idx] + x[row * LDX + 1 + c];
    }
}

// ---------------- GELU (exact) + add_time over 3072 ------------------------
__global__ __launch_bounds__(256) void gelu_time_kernel() {
    int row = blockIdx.x;
    __shared__ float red[8];
    float ss = 0.f;
    for (int c = threadIdx.x; c < MLP; c += 256) {
        float v = g_Sm[row * MLP + c];
        float ge = 0.5f * v * (1.f + erff(v * 0.70710678118654752f));
        g_h3[row * (MLP + 1) + 1 + c] = ge;
        ss += ge * ge;
    }
    ss = block_sum(ss, red);
    if (threadIdx.x == 0) g_h3[row * (MLP + 1)] = sqrtf(1.f + ss);
}

// ---------------- final: out = add_time(Sm2 + res) -------------------------
__global__ __launch_bounds__(256) void final_kernel(float* __restrict__ out) {
    int row = blockIdx.x;
    __shared__ float red[8];
    float vals[3]; float ss = 0.f;
#pragma unroll
    for (int r = 0; r < 3; r++) {
        int c = threadIdx.x + r * 256;
        float f = g_Sk[row * DMODEL + c] + g_res[row * DMODEL + c];
        vals[r] = f; ss += f * f;
    }
    ss = block_sum(ss, red);
#pragma unroll
    for (int r = 0; r < 3; r++) {
        int c = threadIdx.x + r * 256;
        out[row * LDX + 1 + c] = vals[r];
    }
    if (threadIdx.x == 0) out[row * LDX] = sqrtf(1.f + ss);
}

// ---------------- host -----------------------------------------------------
extern "C" void kernel_launch(void* const* d_in, const int* in_sizes, int n_in,
                              void* d_out, int out_size)
{
    const float* x     = (const float*)d_in[0];
    const float* Wq    = (const float*)d_in[1];
    const float* Wk    = (const float*)d_in[2];
    const float* Wv    = (const float*)d_in[3];
    const float* Wo    = (const float*)d_in[4];
    const float* g1    = (const float*)d_in[5];
    const float* b1    = (const float*)d_in[6];
    const float* g2    = (const float*)d_in[7];
    const float* b2    = (const float*)d_in[8];
    const float* Wm1   = (const float*)d_in[9];
    const float* Wm2   = (const float*)d_in[10];
    const float* alpha = (const float*)d_in[11];
    const float* tau   = (const float*)d_in[12];
    const float* lam   = (const float*)d_in[13];
    float* out = (float*)d_out;

    const int ATTN_SMEM = (2 * CHK * 64 + CHK) * 4;   // 66 KB
    const int GEMM_SMEM = 4 * TILEU * 4;
    cudaFuncSetAttribute(attn_kernel, cudaFuncAttributeMaxDynamicSharedMemorySize, ATTN_SMEM);
    cudaFuncSetAttribute(gemm_tf32_kernel, cudaFuncAttributeMaxDynamicSharedMemorySize, GEMM_SMEM);
    cudaFuncSetAttribute(gemm_tf32_qkv_kernel, cudaFuncAttributeMaxDynamicSharedMemorySize, GEMM_SMEM);

    void *ah0, *aSq, *aSk, *aSv, *aSm, *acat, *ah2, *ah3, *ares;
    cudaGetSymbolAddress(&ah0,  g_h0);
    cudaGetSymbolAddress(&aSq,  g_Sq);
    cudaGetSymbolAddress(&aSk,  g_Sk);
    cudaGetSymbolAddress(&aSv,  g_Sv);
    cudaGetSymbolAddress(&aSm,  g_Sm);
    cudaGetSymbolAddress(&acat, g_attncat);
    cudaGetSymbolAddress(&ah2,  g_h2);
    cudaGetSymbolAddress(&ah3,  g_h3);
    cudaGetSymbolAddress(&ares, g_res);

    // 1. LN1
    ln_rows_kernel<<<TOK, 256>>>(x, LDX, 1, g1, b1, (float*)ah0);

    // 2. QKV projections, one launch (z = q/k/v)
    dim3 gqkv(DMODEL / BN, TOK / BM, 3);
    gemm_tf32_qkv_kernel<<<gqkv, 256, GEMM_SMEM>>>(
        (const float*)ah0, Wq, Wk, Wv, (float*)aSq, (float*)aSk, (float*)aSv);

    // 3. q_t, k_t, v_tan
    qkv_post_kernel<<<NBH * SEQ, 64>>>();

    // 4. attention (128 queries / CTA, one per thread)
    dim3 gattn(SEQ / 128, NBH);
    attn_kernel<<<gattn, 128, ATTN_SMEM>>>(alpha, tau, lam);
    attn_time_kernel<<<(TOK + 255) / 256, 256>>>();

    // 5. output projection (So reuses g_Sq)
    dim3 g768(DMODEL / BN, TOK / BM);
    gemm_tf32_kernel<<<g768, 256, GEMM_SMEM>>>((const float*)acat, Wo, (float*)aSq, LDX, LDX, LDX, DMODEL);

    // 6. residual + LN2
    resid_kernel<<<(TOK * DMODEL + 255) / 256, 256>>>(x);
    ln_rows_kernel<<<TOK, 256>>>((const float*)ares, DMODEL, 0, g2, b2, (float*)ah2);

    // 7. MLP up + GELU + add_time
    dim3 gm1(MLP / BN, TOK / BM);
    gemm_tf32_kernel<<<gm1, 256, GEMM_SMEM>>>((const float*)ah2, Wm1, (float*)aSm, LDX, LDX, LDX, MLP);
    gelu_time_kernel<<<TOK, 256>>>();

    // 8. MLP down (Sm2 reuses g_Sk)
    gemm_tf32_kernel<<<g768, 256, GEMM_SMEM>>>((const float*)ah3, Wm2, (float*)aSk, MLP + 1, MLP + 1, MLP + 1, DMODEL);

    // 9. final residual + add_time
    final_kernel<<<TOK, 256>>>(out);
}

// round 12
// speedup vs baseline: 1.0840x; 1.0840x over previous
#include <cuda_runtime.h>
#include <math.h>
#include <stdint.h>

#define TOK    4096
#define DMODEL 768
#define LDX    769
#define NHEAD  12
#define HD     64
#define SEQ    1024
#define NBH    48
#define MLP    3072

// ---------------- scratch (device globals; no allocation allowed) ----------
__device__ float g_h0[TOK * LDX];
__device__ float g_Sq[TOK * DMODEL];
__device__ float g_Sk[TOK * DMODEL];
__device__ float g_Sv[TOK * DMODEL];
__device__ float g_vt[TOK * DMODEL];
__device__ float g_qt[NBH * SEQ];
__device__ float g_kt[NBH * SEQ];
__device__ float g_attncat[TOK * LDX];
__device__ float g_attnt[TOK * NHEAD];
__device__ float g_res[TOK * DMODEL];
__device__ float g_h2[TOK * LDX];
__device__ float g_h3[TOK * (MLP + 1)];
__device__ float g_Sm[TOK * MLP];

// ---------------- helpers --------------------------------------------------
__device__ __forceinline__ float softplusf(float x) {
    return x > 20.f ? x : log1pf(__expf(x));
}

__device__ __forceinline__ uint32_t f2tf32(float v) {
    uint32_t u;
    asm("cvt.rna.tf32.f32 %0, %1;" : "=r"(u) : "f"(v));
    return u;
}

__device__ __forceinline__ unsigned long long fma_f32x2(
    unsigned long long a, unsigned long long b, unsigned long long c) {
    unsigned long long d;
    asm("fma.rn.f32x2 %0, %1, %2, %3;" : "=l"(d) : "l"(a), "l"(b), "l"(c));
    return d;
}
__device__ __forceinline__ unsigned long long pack_f32x2(float lo, float hi) {
    unsigned long long r;
    asm("mov.b64 %0, {%1, %2};" : "=l"(r) : "f"(lo), "f"(hi));
    return r;
}
__device__ __forceinline__ void unpack_f32x2(unsigned long long v, float& lo, float& hi) {
    asm("mov.b64 {%0, %1}, %2;" : "=f"(lo), "=f"(hi) : "l"(v));
}

__device__ __forceinline__ float block_sum(float v, float* red) {
#pragma unroll
    for (int o = 16; o > 0; o >>= 1) v += __shfl_xor_sync(0xffffffffu, v, o);
    int w = threadIdx.x >> 5;
    int nw = blockDim.x >> 5;
    if ((threadIdx.x & 31) == 0) red[w] = v;
    __syncthreads();
    float r = 0.f;
    for (int i = 0; i < nw; i++) r += red[i];
    __syncthreads();
    return r;
}

// ---------------- LayerNorm over 768 spatial dims, write [t, s] (769) ------
__global__ __launch_bounds__(256) void ln_rows_kernel(
    const float* __restrict__ in, int ld, int off,
    const float* __restrict__ gam, const float* __restrict__ bet,
    float* __restrict__ out)
{
    int row = blockIdx.x;
    const float* xr = in + row * ld + off;
    __shared__ float red[8];
    float v[3];
    float s1 = 0.f, s2 = 0.f;
#pragma unroll
    for (int r = 0; r < 3; r++) {
        int c = threadIdx.x + r * 256;
        float x = xr[c];
        v[r] = x; s1 += x; s2 += x * x;
    }
    s1 = block_sum(s1, red);
    s2 = block_sum(s2, red);
    float mu = s1 * (1.f / DMODEL);
    float var = s2 * (1.f / DMODEL) - mu * mu;
    float rstd = rsqrtf(var + 1e-5f);
    float ss = 0.f;
#pragma unroll
    for (int r = 0; r < 3; r++) {
        int c = threadIdx.x + r * 256;
        float nv = (v[r] - mu) * rstd * gam[c] + bet[c];
        out[row * LDX + 1 + c] = nv;
        ss += nv * nv;
    }
    ss = block_sum(ss, red);
    if (threadIdx.x == 0) out[row * LDX] = sqrtf(1.f + ss);
}

// ---------------- tf32 tensor-core GEMM (double-buffered) ------------------
#define BM 128
#define BN 128
#define BK 32
#define SKP 36
#define TILEU (BM * SKP)

__device__ __forceinline__ void gemm_body(
    const float* __restrict__ A, const float* __restrict__ B,
    float* __restrict__ C, int K, int lda, int ldb, int ldc,
    uint32_t* As, uint32_t* Bs, int m0, int n0)
{
    int tid  = threadIdx.x;
    int lane = tid & 31;
    int warp = tid >> 5;
    int warp_m = (warp >> 1) * 32;
    int warp_n = (warp & 1) * 64;
    int frow = lane >> 2;
    int fk   = lane & 3;
    int lm = tid >> 5;
    int lk = tid & 31;

    float acc[2][8][4];
#pragma unroll
    for (int i = 0; i < 2; i++)
#pragma unroll
        for (int j = 0; j < 8; j++)
#pragma unroll
            for (int c = 0; c < 4; c++) acc[i][j][c] = 0.f;

    int nT = (K + BK - 1) / BK;
    float aReg[16], bReg[16];

#pragma unroll
    for (int it = 0; it < 16; it++) {
        int m = lm + it * 8;
        aReg[it] = (lk < K) ? A[(m0 + m) * lda + lk] : 0.f;
        bReg[it] = (lk < K) ? B[(n0 + m) * ldb + lk] : 0.f;
    }
#pragma unroll
    for (int it = 0; it < 16; it++) {
        int m = lm + it * 8;
        As[m * SKP + lk] = f2tf32(aReg[it]);
        Bs[m * SKP + lk] = f2tf32(bReg[it]);
    }
    __syncthreads();

    for (int t = 0; t < nT; t++) {
        uint32_t* Ab = As + (t & 1) * TILEU;
        uint32_t* Bb = Bs + (t & 1) * TILEU;

        if (t + 1 < nT) {
            int k0 = (t + 1) * BK;
#pragma unroll
            for (int it = 0; it < 16; it++) {
                int m = lm + it * 8;
                int kk = k0 + lk;
                aReg[it] = (kk < K) ? A[(m0 + m) * lda + kk] : 0.f;
                bReg[it] = (kk < K) ? B[(n0 + m) * ldb + kk] : 0.f;
            }
        }

#pragma unroll
        for (int ks = 0; ks < 4; ks++) {
            int kb = ks * 8 + fk;
            uint32_t a[2][4];
#pragma unroll
            for (int i = 0; i < 2; i++) {
                int mr = warp_m + i * 16 + frow;
                a[i][0] = Ab[mr * SKP + kb];
                a[i][1] = Ab[(mr + 8) * SKP + kb];
                a[i][2] = Ab[mr * SKP + kb + 4];
                a[i][3] = Ab[(mr + 8) * SKP + kb + 4];
            }
#pragma unroll
            for (int j = 0; j < 8; j++) {
                int nr = warp_n + j * 8 + frow;
                uint32_t b0 = Bb[nr * SKP + kb];
                uint32_t b1 = Bb[nr * SKP + kb + 4];
#pragma unroll
                for (int i = 0; i < 2; i++) {
                    asm volatile(
                        "mma.sync.aligned.m16n8k8.row.col.f32.tf32.tf32.f32 "
                        "{%0,%1,%2,%3}, {%4,%5,%6,%7}, {%8,%9}, {%0,%1,%2,%3};"
                        : "+f"(acc[i][j][0]), "+f"(acc[i][j][1]),
                          "+f"(acc[i][j][2]), "+f"(acc[i][j][3])
                        : "r"(a[i][0]), "r"(a[i][1]), "r"(a[i][2]), "r"(a[i][3]),
                          "r"(b0), "r"(b1));
                }
            }
        }

        if (t + 1 < nT) {
            uint32_t* An = As + ((t + 1) & 1) * TILEU;
            uint32_t* Bn = Bs + ((t + 1) & 1) * TILEU;
#pragma unroll
            for (int it = 0; it < 16; it++) {
                int m = lm + it * 8;
                An[m * SKP + lk] = f2tf32(aReg[it]);
                Bn[m * SKP + lk] = f2tf32(bReg[it]);
            }
            __syncthreads();
        }
    }

#pragma unroll
    for (int i = 0; i < 2; i++) {
#pragma unroll
        for (int j = 0; j < 8; j++) {
            int row = m0 + warp_m + i * 16 + frow;
            int col = n0 + warp_n + j * 8 + fk * 2;
            C[row * ldc + col]           = acc[i][j][0];
            C[row * ldc + col + 1]       = acc[i][j][1];
            C[(row + 8) * ldc + col]     = acc[i][j][2];
            C[(row + 8) * ldc + col + 1] = acc[i][j][3];
        }
    }
}

__global__ __launch_bounds__(256, 2) void gemm_tf32_kernel(
    const float* __restrict__ A, const float* __restrict__ B,
    float* __restrict__ C, int K, int lda, int ldb, int ldc)
{
    extern __shared__ uint32_t smemU[];
    gemm_body(A, B, C, K, lda, ldb, ldc,
              smemU, smemU + 2 * TILEU, blockIdx.y * BM, blockIdx.x * BN);
}

__global__ __launch_bounds__(256, 2) void gemm_tf32_qkv_kernel(
    const float* __restrict__ A,
    const float* __restrict__ Wq, const float* __restrict__ Wk, const float* __restrict__ Wv,
    float* __restrict__ Sq, float* __restrict__ Sk, float* __restrict__ Sv)
{
    extern __shared__ uint32_t smemU[];
    const float* B = (blockIdx.z == 0) ? Wq : (blockIdx.z == 1) ? Wk : Wv;
    float* C       = (blockIdx.z == 0) ? Sq : (blockIdx.z == 1) ? Sk : Sv;
    gemm_body(A, B, C, LDX, LDX, LDX, DMODEL,
              smemU, smemU + 2 * TILEU, blockIdx.y * BM, blockIdx.x * BN);
}

// ---------------- QKV epilogue: q_t, k_t, v_tan ----------------------------
__global__ __launch_bounds__(64) void qkv_post_kernel() {
    int gid = blockIdx.x;             // bh*SEQ + i
    int bh = gid >> 10, i = gid & 1023;
    int b = bh / NHEAD, h = bh % NHEAD;
    int off = (b * SEQ + i) * DMODEL + h * HD + threadIdx.x;
    float q = g_Sq[off], k = g_Sk[off], vv = g_Sv[off];
    float sq = q * q, sk = k * k, sv = vv * vv;
#pragma unroll
    for (int o = 16; o > 0; o >>= 1) {
        sq += __shfl_xor_sync(0xffffffffu, sq, o);
        sk += __shfl_xor_sync(0xffffffffu, sk, o);
        sv += __shfl_xor_sync(0xffffffffu, sv, o);
    }
    __shared__ float red[6];
    if ((threadIdx.x & 31) == 0) {
        int w = threadIdx.x >> 5;
        red[w * 3 + 0] = sq; red[w * 3 + 1] = sk; red[w * 3 + 2] = sv;
    }
    __syncthreads();
    float Sq2 = red[0] + red[3], Sk2 = red[1] + red[4], Sv2 = red[2] + red[5];
    if (threadIdx.x == 0) {
        g_qt[gid] = sqrtf(1.f + Sq2);
        g_kt[gid] = sqrtf(1.f + Sk2);
    }
    float vt_time = sqrtf(1.f + Sv2);
    float sn = sqrtf(Sv2);
    float dist = acoshf(fmaxf(vt_time, 1.f + 1e-7f));
    g_vt[off] = vv * (dist / fmaxf(sn, 1e-8f));
}

// ---------------- attention v4: one query per thread, fixed-ref softmax ----
// Logits provably < 0, so exp w.r.t. reference 0 is safe (no running max).
// Dot product split into 4 independent FMA2 chains: dep depth 128 -> 32 cyc.
// dyn smem floats: kc[128*64] | vc[128*64] | ktc[128]
#define CHK 128
__global__ __launch_bounds__(128, 3) void attn_kernel(
    const float* __restrict__ alpha_p, const float* __restrict__ tau_p,
    const float* __restrict__ lam_p)
{
    extern __shared__ float smdyn[];
    float* kc  = smdyn;
    float* vc  = smdyn + CHK * 64;
    float* ktc = smdyn + 2 * CHK * 64;

    int tid = threadIdx.x;
    int bh = blockIdx.y;
    int b = bh / NHEAD, h = bh % NHEAD;
    int i = blockIdx.x * 128 + tid;
    int tokbase = b * SEQ;

    float tau = softplusf(tau_p[0]);
    float lam = softplusf(lam_p[0]);
    float alpha = softplusf(alpha_p[0]);

    const float* qrow = g_Sq + (tokbase + i) * DMODEL + h * HD;
    unsigned long long q2[32];
#pragma unroll
    for (int dd = 0; dd < 32; dd++)
        q2[dd] = *reinterpret_cast<const unsigned long long*>(qrow + 2 * dd);

    float qt = g_qt[bh * SEQ + i];
    float coshOQ = fmaxf(qt, 1.f + 1e-7f);
    float c_t = fminf(acoshf(coshOQ), 40.f);
    float isOQ = 1.f / sinhf(c_t);
    float Bv = alpha * c_t / (1.f + alpha * c_t);

    float S = 0.f;
    unsigned long long acc2[32];
#pragma unroll
    for (int dd = 0; dd < 32; dd++) acc2[dd] = 0ull;

    for (int jc = 0; jc < SEQ; jc += CHK) {
        __syncthreads();
        for (int idx = tid; idx < CHK * 16; idx += 128) {
            int row = idx >> 4, c4 = idx & 15;
            const float* src = g_Sk + (tokbase + jc + row) * DMODEL + h * HD + c4 * 4;
            *reinterpret_cast<float4*>(kc + row * 64 + c4 * 4) =
                *reinterpret_cast<const float4*>(src);
            const float* srcv = g_vt + (tokbase + jc + row) * DMODEL + h * HD + c4 * 4;
            *reinterpret_cast<float4*>(vc + row * 64 + c4 * 4) =
                *reinterpret_cast<const float4*>(srcv);
        }
        if (tid < CHK) ktc[tid] = g_kt[bh * SEQ + jc + tid];
        __syncthreads();

        for (int j = 0; j < CHK; j++) {
            const ulonglong2* kr = reinterpret_cast<const ulonglong2*>(kc + j * 64);
            // 4 independent FMA2 chains (dep depth 8 each)
            unsigned long long dA = 0ull, dB = 0ull, dC = 0ull, dD = 0ull;
#pragma unroll
            for (int dd = 0; dd < 8; dd++) {
                ulonglong2 k0 = kr[2 * dd];
                ulonglong2 k1 = kr[2 * dd + 1];
                dA = fma_f32x2(q2[4 * dd],     k0.x, dA);
                dB = fma_f32x2(q2[4 * dd + 1], k0.y, dB);
                dC = fma_f32x2(q2[4 * dd + 2], k1.x, dC);
                dD = fma_f32x2(q2[4 * dd + 3], k1.y, dD);
            }
            float aL, aH, bL, bH, cL, cH, eL, eH;
            unpack_f32x2(dA, aL, aH); unpack_f32x2(dB, bL, bH);
            unpack_f32x2(dC, cL, cH); unpack_f32x2(dD, eL, eH);
            float dot = ((aL + aH) + (bL + bH)) + ((cL + cH) + (eL + eH));

            float kt = ktc[j];
            float coshOK = fmaxf(kt, 1.f + 1e-7f);
            float raw_cosh = fmaxf(qt * kt - dot, 1.f);
            bool is_self = raw_cosh < 1.f + 1e-5f;
            float safe_cosh = is_self ? 2.f : raw_cosh;
            float t2 = safe_cosh * safe_cosh - 1.f;
            float invs = rsqrtf(t2);
            float sh = t2 * invs;
            float dist = __logf(safe_cosh + sh);
            float rawZ = (raw_cosh * coshOQ - coshOK) * isOQ * invs;
            float Z = is_self ? 1.f : fminf(fmaxf(rawZ, -1.f), 1.f);
            float dL = fminf(dist, 40.f);
            float lp = -lam * __logf(1.f + dL * dL);
            float xe = Bv + Z - 0.1f;
            float ent = __logf(1.f + __expf(xe));
            float l = lp - tau * ent;          // provably < 0

            float e = __expf(l);
            S += e;
            unsigned long long e2 = pack_f32x2(e, e);
            const ulonglong2* vr = reinterpret_cast<const ulonglong2*>(vc + j * 64);
#pragma unroll
            for (int dd = 0; dd < 16; dd++) {
                ulonglong2 vv = vr[dd];
                acc2[2 * dd]     = fma_f32x2(vv.x, e2, acc2[2 * dd]);
                acc2[2 * dd + 1] = fma_f32x2(vv.y, e2, acc2[2 * dd + 1]);
            }
        }
    }

    // epilogue: normalize, expmap0, write (all thread-local)
    float inv = 1.f / S;
    float a[64];
    float n2 = 0.f;
#pragma unroll
    for (int dd = 0; dd < 32; dd++) {
        float lo, hi; unpack_f32x2(acc2[dd], lo, hi);
        lo *= inv; hi *= inv;
        a[2 * dd] = lo; a[2 * dd + 1] = hi;
        n2 += lo * lo + hi * hi;
    }
    float nn = sqrtf(n2);
    float tt = coshf(nn);
    float sf = sinhf(nn) / fmaxf(nn, 1e-8f);
    float* orow = g_attncat + (tokbase + i) * LDX + 1 + h * HD;
#pragma unroll
    for (int d = 0; d < 64; d++) orow[d] = a[d] * sf;
    g_attnt[(tokbase + i) * NHEAD + h] = tt;
}

// ---------------- t_new = sqrt(sum_h t_h^2 - 11) ---------------------------
__global__ void attn_time_kernel() {
    int t = blockIdx.x * 256 + threadIdx.x;
    if (t < TOK) {
        float s = 0.f;
#pragma unroll
        for (int hh = 0; hh < NHEAD; hh++) { float a = g_attnt[t * NHEAD + hh]; s += a * a; }
        g_attncat[t * LDX] = sqrtf(s - (float)(NHEAD - 1));
    }
}

// ---------------- residual: res = So + x_s ---------------------------------
__global__ void resid_kernel(const float* __restrict__ x) {
    int idx = blockIdx.x * 256 + threadIdx.x;
    if (idx < TOK * DMODEL) {
        int row = idx / DMODEL, c = idx % DMODEL;
        g_res[idx] = g_Sq[idx] + x[row * LDX + 1 + c];
    }
}

// ---------------- GELU (exact) + add_time over 3072 ------------------------
__global__ __launch_bounds__(256) void gelu_time_kernel() {
    int row = blockIdx.x;
    __shared__ float red[8];
    float ss = 0.f;
    for (int c = threadIdx.x; c < MLP; c += 256) {
        float v = g_Sm[row * MLP + c];
        float ge = 0.5f * v * (1.f + erff(v * 0.70710678118654752f));
        g_h3[row * (MLP + 1) + 1 + c] = ge;
        ss += ge * ge;
    }
    ss = block_sum(ss, red);
    if (threadIdx.x == 0) g_h3[row * (MLP + 1)] = sqrtf(1.f + ss);
}

// ---------------- final: out = add_time(Sm2 + res) -------------------------
__global__ __launch_bounds__(256) void final_kernel(float* __restrict__ out) {
    int row = blockIdx.x;
    __shared__ float red[8];
    float vals[3]; float ss = 0.f;
#pragma unroll
    for (int r = 0; r < 3; r++) {
        int c = threadIdx.x + r * 256;
        float f = g_Sk[row * DMODEL + c] + g_res[row * DMODEL + c];
        vals[r] = f; ss += f * f;
    }
    ss = block_sum(ss, red);
#pragma unroll
    for (int r = 0; r < 3; r++) {
        int c = threadIdx.x + r * 256;
        out[row * LDX + 1 + c] = vals[r];
    }
    if (threadIdx.x == 0) out[row * LDX] = sqrtf(1.f + ss);
}

// ---------------- host -----------------------------------------------------
extern "C" void kernel_launch(void* const* d_in, const int* in_sizes, int n_in,
                              void* d_out, int out_size)
{
    const float* x     = (const float*)d_in[0];
    const float* Wq    = (const float*)d_in[1];
    const float* Wk    = (const float*)d_in[2];
    const float* Wv    = (const float*)d_in[3];
    const float* Wo    = (const float*)d_in[4];
    const float* g1    = (const float*)d_in[5];
    const float* b1    = (const float*)d_in[6];
    const float* g2    = (const float*)d_in[7];
    const float* b2    = (const float*)d_in[8];
    const float* Wm1   = (const float*)d_in[9];
    const float* Wm2   = (const float*)d_in[10];
    const float* alpha = (const float*)d_in[11];
    const float* tau   = (const float*)d_in[12];
    const float* lam   = (const float*)d_in[13];
    float* out = (float*)d_out;

    const int ATTN_SMEM = (2 * CHK * 64 + CHK) * 4;   // 66 KB
    const int GEMM_SMEM = 4 * TILEU * 4;
    cudaFuncSetAttribute(attn_kernel, cudaFuncAttributeMaxDynamicSharedMemorySize, ATTN_SMEM);
    cudaFuncSetAttribute(gemm_tf32_kernel, cudaFuncAttributeMaxDynamicSharedMemorySize, GEMM_SMEM);
    cudaFuncSetAttribute(gemm_tf32_qkv_kernel, cudaFuncAttributeMaxDynamicSharedMemorySize, GEMM_SMEM);

    void *ah0, *aSq, *aSk, *aSv, *aSm, *acat, *ah2, *ah3, *ares;
    cudaGetSymbolAddress(&ah0,  g_h0);
    cudaGetSymbolAddress(&aSq,  g_Sq);
    cudaGetSymbolAddress(&aSk,  g_Sk);
    cudaGetSymbolAddress(&aSv,  g_Sv);
    cudaGetSymbolAddress(&aSm,  g_Sm);
    cudaGetSymbolAddress(&acat, g_attncat);
    cudaGetSymbolAddress(&ah2,  g_h2);
    cudaGetSymbolAddress(&ah3,  g_h3);
    cudaGetSymbolAddress(&ares, g_res);

    // 1. LN1
    ln_rows_kernel<<<TOK, 256>>>(x, LDX, 1, g1, b1, (float*)ah0);

    // 2. QKV projections, one launch (z = q/k/v)
    dim3 gqkv(DMODEL / BN, TOK / BM, 3);
    gemm_tf32_qkv_kernel<<<gqkv, 256, GEMM_SMEM>>>(
        (const float*)ah0, Wq, Wk, Wv, (float*)aSq, (float*)aSk, (float*)aSv);

    // 3. q_t, k_t, v_tan
    qkv_post_kernel<<<NBH * SEQ, 64>>>();

    // 4. attention (128 queries / CTA, one per thread)
    dim3 gattn(SEQ / 128, NBH);
    attn_kernel<<<gattn, 128, ATTN_SMEM>>>(alpha, tau, lam);
    attn_time_kernel<<<(TOK + 255) / 256, 256>>>();

    // 5. output projection (So reuses g_Sq)
    dim3 g768(DMODEL / BN, TOK / BM);
    gemm_tf32_kernel<<<g768, 256, GEMM_SMEM>>>((const float*)acat, Wo, (float*)aSq, LDX, LDX, LDX, DMODEL);

    // 6. residual + LN2
    resid_kernel<<<(TOK * DMODEL + 255) / 256, 256>>>(x);
    ln_rows_kernel<<<TOK, 256>>>((const float*)ares, DMODEL, 0, g2, b2, (float*)ah2);

    // 7. MLP up + GELU + add_time
    dim3 gm1(MLP / BN, TOK / BM);
    gemm_tf32_kernel<<<gm1, 256, GEMM_SMEM>>>((const float*)ah2, Wm1, (float*)aSm, LDX, LDX, LDX, MLP);
    gelu_time_kernel<<<TOK, 256>>>();

    // 8. MLP down (Sm2 reuses g_Sk)
    gemm_tf32_kernel<<<g768, 256, GEMM_SMEM>>>((const float*)ah3, Wm2, (float*)aSk, MLP + 1, MLP + 1, MLP + 1, DMODEL);

    // 9. final residual + add_time
    final_kernel<<<TOK, 256>>>(out);
}

// round 15
// speedup vs baseline: 1.4337x; 1.3226x over previous
#include <cuda_runtime.h>
#include <math.h>
#include <stdint.h>

#define TOK    4096
#define DMODEL 768
#define LDX    769
#define NHEAD  12
#define HD     64
#define SEQ    1024
#define NBH    48
#define MLP    3072

// ---------------- scratch (device globals; no allocation allowed) ----------
__device__ float g_h0[TOK * LDX];
__device__ float g_Sq[TOK * DMODEL];
__device__ float g_Sk[TOK * DMODEL];
__device__ float g_Sv[TOK * DMODEL];
__device__ float g_vt[TOK * DMODEL];
__device__ float g_qt[NBH * SEQ];
__device__ float g_kt[NBH * SEQ];
__device__ float g_attncat[TOK * LDX];
__device__ float g_attnt[TOK * NHEAD];
__device__ float g_res[TOK * DMODEL];
__device__ float g_h2[TOK * LDX];
__device__ float g_h3[TOK * (MLP + 1)];
__device__ float g_Sm[TOK * MLP];

// ---------------- helpers --------------------------------------------------
__device__ __forceinline__ float softplusf(float x) {
    return x > 20.f ? x : log1pf(__expf(x));
}

__device__ __forceinline__ uint32_t f2tf32(float v) {
    uint32_t u;
    asm("cvt.rna.tf32.f32 %0, %1;" : "=r"(u) : "f"(v));
    return u;
}

__device__ __forceinline__ void mma_tf32(float* c,
    uint32_t a0, uint32_t a1, uint32_t a2, uint32_t a3,
    uint32_t b0, uint32_t b1)
{
    asm volatile(
        "mma.sync.aligned.m16n8k8.row.col.f32.tf32.tf32.f32 "
        "{%0,%1,%2,%3}, {%4,%5,%6,%7}, {%8,%9}, {%0,%1,%2,%3};"
        : "+f"(c[0]), "+f"(c[1]), "+f"(c[2]), "+f"(c[3])
        : "r"(a0), "r"(a1), "r"(a2), "r"(a3), "r"(b0), "r"(b1));
}

__device__ __forceinline__ float block_sum(float v, float* red) {
#pragma unroll
    for (int o = 16; o > 0; o >>= 1) v += __shfl_xor_sync(0xffffffffu, v, o);
    int w = threadIdx.x >> 5;
    int nw = blockDim.x >> 5;
    if ((threadIdx.x & 31) == 0) red[w] = v;
    __syncthreads();
    float r = 0.f;
    for (int i = 0; i < nw; i++) r += red[i];
    __syncthreads();
    return r;
}

// ---------------- LayerNorm over 768 spatial dims, write [t, s] (769) ------
__global__ __launch_bounds__(256) void ln_rows_kernel(
    const float* __restrict__ in, int ld, int off,
    const float* __restrict__ gam, const float* __restrict__ bet,
    float* __restrict__ out)
{
    int row = blockIdx.x;
    const float* xr = in + row * ld + off;
    __shared__ float red[8];
    float v[3];
    float s1 = 0.f, s2 = 0.f;
#pragma unroll
    for (int r = 0; r < 3; r++) {
        int c = threadIdx.x + r * 256;
        float x = xr[c];
        v[r] = x; s1 += x; s2 += x * x;
    }
    s1 = block_sum(s1, red);
    s2 = block_sum(s2, red);
    float mu = s1 * (1.f / DMODEL);
    float var = s2 * (1.f / DMODEL) - mu * mu;
    float rstd = rsqrtf(var + 1e-5f);
    float ss = 0.f;
#pragma unroll
    for (int r = 0; r < 3; r++) {
        int c = threadIdx.x + r * 256;
        float nv = (v[r] - mu) * rstd * gam[c] + bet[c];
        out[row * LDX + 1 + c] = nv;
        ss += nv * nv;
    }
    ss = block_sum(ss, red);
    if (threadIdx.x == 0) out[row * LDX] = sqrtf(1.f + ss);
}

// ---------------- tf32 tensor-core GEMM (double-buffered) ------------------
#define BM 128
#define BN 128
#define BK 32
#define SKP 36
#define TILEU (BM * SKP)

__device__ __forceinline__ void gemm_body(
    const float* __restrict__ A, const float* __restrict__ B,
    float* __restrict__ C, int K, int lda, int ldb, int ldc,
    uint32_t* As, uint32_t* Bs, int m0, int n0)
{
    int tid  = threadIdx.x;
    int lane = tid & 31;
    int warp = tid >> 5;
    int warp_m = (warp >> 1) * 32;
    int warp_n = (warp & 1) * 64;
    int frow = lane >> 2;
    int fk   = lane & 3;
    int lm = tid >> 5;
    int lk = tid & 31;

    float acc[2][8][4];
#pragma unroll
    for (int i = 0; i < 2; i++)
#pragma unroll
        for (int j = 0; j < 8; j++)
#pragma unroll
            for (int c = 0; c < 4; c++) acc[i][j][c] = 0.f;

    int nT = (K + BK - 1) / BK;
    float aReg[16], bReg[16];

#pragma unroll
    for (int it = 0; it < 16; it++) {
        int m = lm + it * 8;
        aReg[it] = (lk < K) ? A[(m0 + m) * lda + lk] : 0.f;
        bReg[it] = (lk < K) ? B[(n0 + m) * ldb + lk] : 0.f;
    }
#pragma unroll
    for (int it = 0; it < 16; it++) {
        int m = lm + it * 8;
        As[m * SKP + lk] = f2tf32(aReg[it]);
        Bs[m * SKP + lk] = f2tf32(bReg[it]);
    }
    __syncthreads();

    for (int t = 0; t < nT; t++) {
        uint32_t* Ab = As + (t & 1) * TILEU;
        uint32_t* Bb = Bs + (t & 1) * TILEU;

        if (t + 1 < nT) {
            int k0 = (t + 1) * BK;
#pragma unroll
            for (int it = 0; it < 16; it++) {
                int m = lm + it * 8;
                int kk = k0 + lk;
                aReg[it] = (kk < K) ? A[(m0 + m) * lda + kk] : 0.f;
                bReg[it] = (kk < K) ? B[(n0 + m) * ldb + kk] : 0.f;
            }
        }

#pragma unroll
        for (int ks = 0; ks < 4; ks++) {
            int kb = ks * 8 + fk;
            uint32_t a[2][4];
#pragma unroll
            for (int i = 0; i < 2; i++) {
                int mr = warp_m + i * 16 + frow;
                a[i][0] = Ab[mr * SKP + kb];
                a[i][1] = Ab[(mr + 8) * SKP + kb];
                a[i][2] = Ab[mr * SKP + kb + 4];
                a[i][3] = Ab[(mr + 8) * SKP + kb + 4];
            }
#pragma unroll
            for (int j = 0; j < 8; j++) {
                int nr = warp_n + j * 8 + frow;
                uint32_t b0 = Bb[nr * SKP + kb];
                uint32_t b1 = Bb[nr * SKP + kb + 4];
#pragma unroll
                for (int i = 0; i < 2; i++)
                    mma_tf32(acc[i][j], a[i][0], a[i][1], a[i][2], a[i][3], b0, b1);
            }
        }

        if (t + 1 < nT) {
            uint32_t* An = As + ((t + 1) & 1) * TILEU;
            uint32_t* Bn = Bs + ((t + 1) & 1) * TILEU;
#pragma unroll
            for (int it = 0; it < 16; it++) {
                int m = lm + it * 8;
                An[m * SKP + lk] = f2tf32(aReg[it]);
                Bn[m * SKP + lk] = f2tf32(bReg[it]);
            }
            __syncthreads();
        }
    }

#pragma unroll
    for (int i = 0; i < 2; i++) {
#pragma unroll
        for (int j = 0; j < 8; j++) {
            int row = m0 + warp_m + i * 16 + frow;
            int col = n0 + warp_n + j * 8 + fk * 2;
            C[row * ldc + col]           = acc[i][j][0];
            C[row * ldc + col + 1]       = acc[i][j][1];
            C[(row + 8) * ldc + col]     = acc[i][j][2];
            C[(row + 8) * ldc + col + 1] = acc[i][j][3];
        }
    }
}

__global__ __launch_bounds__(256, 2) void gemm_tf32_kernel(
    const float* __restrict__ A, const float* __restrict__ B,
    float* __restrict__ C, int K, int lda, int ldb, int ldc)
{
    extern __shared__ uint32_t smemU[];
    gemm_body(A, B, C, K, lda, ldb, ldc,
              smemU, smemU + 2 * TILEU, blockIdx.y * BM, blockIdx.x * BN);
}

__global__ __launch_bounds__(256, 2) void gemm_tf32_qkv_kernel(
    const float* __restrict__ A,
    const float* __restrict__ Wq, const float* __restrict__ Wk, const float* __restrict__ Wv,
    float* __restrict__ Sq, float* __restrict__ Sk, float* __restrict__ Sv)
{
    extern __shared__ uint32_t smemU[];
    const float* B = (blockIdx.z == 0) ? Wq : (blockIdx.z == 1) ? Wk : Wv;
    float* C       = (blockIdx.z == 0) ? Sq : (blockIdx.z == 1) ? Sk : Sv;
    gemm_body(A, B, C, LDX, LDX, LDX, DMODEL,
              smemU, smemU + 2 * TILEU, blockIdx.y * BM, blockIdx.x * BN);
}

// ---------------- QKV epilogue: q_t, k_t, v_tan ----------------------------
__global__ __launch_bounds__(64) void qkv_post_kernel() {
    int gid = blockIdx.x;             // bh*SEQ + i
    int bh = gid >> 10, i = gid & 1023;
    int b = bh / NHEAD, h = bh % NHEAD;
    int off = (b * SEQ + i) * DMODEL + h * HD + threadIdx.x;
    float q = g_Sq[off], k = g_Sk[off], vv = g_Sv[off];
    float sq = q * q, sk = k * k, sv = vv * vv;
#pragma unroll
    for (int o = 16; o > 0; o >>= 1) {
        sq += __shfl_xor_sync(0xffffffffu, sq, o);
        sk += __shfl_xor_sync(0xffffffffu, sk, o);
        sv += __shfl_xor_sync(0xffffffffu, sv, o);
    }
    __shared__ float red[6];
    if ((threadIdx.x & 31) == 0) {
        int w = threadIdx.x >> 5;
        red[w * 3 + 0] = sq; red[w * 3 + 1] = sk; red[w * 3 + 2] = sv;
    }
    __syncthreads();
    float Sq2 = red[0] + red[3], Sk2 = red[1] + red[4], Sv2 = red[2] + red[5];
    if (threadIdx.x == 0) {
        g_qt[gid] = sqrtf(1.f + Sq2);
        g_kt[gid] = sqrtf(1.f + Sk2);
    }
    float vt_time = sqrtf(1.f + Sv2);
    float sn = sqrtf(Sv2);
    float dist = acoshf(fmaxf(vt_time, 1.f + 1e-7f));
    g_vt[off] = vv * (dist / fmaxf(sn, 1e-8f));
}

// ---------------- attention v5b: tensor-core flash (tf32 mma) --------------
// CTA = 128 threads (4 warps), 64-query tile, K/V chunks of 64.
// S = Q@K^T via m16n8k8; per-element hyperbolic transform on C-frags;
// P (tf32) staged to smem, fed back as A-frags for P@V mma.
// is_self is the reference's VALUE TEST ONLY (no diagonal special-case).
// Fixed-ref softmax (logits provably < 0) -> running scalar sum only.
// smem u32[4*64*72] = 72KB: Qs | Kc | Vc | Pc, pitch 72.
//   Qs[row*72+64..67] = {qt, coshOQ, isOQ, Bv};  Kc[j*72+64] = k_t.
#define AKP 72
#define ATILE (64 * AKP)

__device__ __forceinline__ float pair_e(
    float dot, float kt, float qt, float cOQ, float isOQ, float Bv,
    float tau, float lam)
{
    float coshOK = fmaxf(kt, 1.f + 1e-7f);
    float raw_cosh = fmaxf(qt * kt - dot, 1.f);
    bool is_self = raw_cosh < 1.f + 1e-5f;
    float safe_cosh = is_self ? 2.f : raw_cosh;
    float t2 = safe_cosh * safe_cosh - 1.f;
    float invs = rsqrtf(t2);
    float sh = t2 * invs;
    float dist = __logf(safe_cosh + sh);
    float rawZ = (raw_cosh * cOQ - coshOK) * isOQ * invs;
    float Z = is_self ? 1.f : fminf(fmaxf(rawZ, -1.f), 1.f);
    float dL = fminf(dist, 40.f);
    float lp = -lam * __logf(1.f + dL * dL);
    float xe = Bv + Z - 0.1f;
    float ent = __logf(1.f + __expf(xe));
    return __expf(lp - tau * ent);        // logit < 0 always
}

__global__ __launch_bounds__(128, 3) void attn_kernel(
    const float* __restrict__ alpha_p, const float* __restrict__ tau_p,
    const float* __restrict__ lam_p)
{
    extern __shared__ uint32_t smA[];
    uint32_t* Qs = smA;
    uint32_t* Kc = smA + ATILE;
    uint32_t* Vc = smA + 2 * ATILE;
    uint32_t* Pc = smA + 3 * ATILE;

    int tid  = threadIdx.x;
    int lane = tid & 31;
    int warp = tid >> 5;
    int frow = lane >> 2;
    int fk   = lane & 3;
    int qbase = warp * 16;
    int bh = blockIdx.y;
    int b = bh / NHEAD, h = bh % NHEAD;
    int i0 = blockIdx.x * 64;
    int tokbase = b * SEQ;

    float tau = softplusf(tau_p[0]);
    float lam = softplusf(lam_p[0]);
    float alpha = softplusf(alpha_p[0]);

    // stage Q (tf32) + per-row scalars into Qs padding
    for (int idx = tid; idx < 64 * 16; idx += 128) {
        int row = idx >> 4, c4 = idx & 15;
        float4 v = *reinterpret_cast<const float4*>(
            g_Sq + (tokbase + i0 + row) * DMODEL + h * HD + c4 * 4);
        uint4 u = { f2tf32(v.x), f2tf32(v.y), f2tf32(v.z), f2tf32(v.w) };
        *reinterpret_cast<uint4*>(Qs + row * AKP + c4 * 4) = u;
    }
    if (tid < 64) {
        float qt = g_qt[bh * SEQ + i0 + tid];
        float cOQ = fmaxf(qt, 1.f + 1e-7f);
        float c_t = fminf(acoshf(cOQ), 40.f);
        float isOQ = 1.f / sinhf(c_t);
        float Bv = alpha * c_t / (1.f + alpha * c_t);
        Qs[tid * AKP + 64] = __float_as_uint(qt);
        Qs[tid * AKP + 65] = __float_as_uint(cOQ);
        Qs[tid * AKP + 66] = __float_as_uint(isOQ);
        Qs[tid * AKP + 67] = __float_as_uint(Bv);
    }
    __syncthreads();

    int rowA = qbase + frow, rowB = qbase + frow + 8;
    float qtA  = __uint_as_float(Qs[rowA * AKP + 64]);
    float cOQA = __uint_as_float(Qs[rowA * AKP + 65]);
    float isA  = __uint_as_float(Qs[rowA * AKP + 66]);
    float BvA  = __uint_as_float(Qs[rowA * AKP + 67]);
    float qtB  = __uint_as_float(Qs[rowB * AKP + 64]);
    float cOQB = __uint_as_float(Qs[rowB * AKP + 65]);
    float isB  = __uint_as_float(Qs[rowB * AKP + 66]);
    float BvB  = __uint_as_float(Qs[rowB * AKP + 67]);

    float Oacc[8][4];
#pragma unroll
    for (int nt = 0; nt < 8; nt++)
#pragma unroll
        for (int c = 0; c < 4; c++) Oacc[nt][c] = 0.f;
    float sumA = 0.f, sumB = 0.f;

    for (int jc = 0; jc < SEQ; jc += 64) {
        __syncthreads();   // prior chunk's Kc/Vc/Pc readers done
        for (int idx = tid; idx < 64 * 16; idx += 128) {
            int row = idx >> 4, c4 = idx & 15;
            const float* ksrc = g_Sk + (tokbase + jc + row) * DMODEL + h * HD + c4 * 4;
            float4 kv = *reinterpret_cast<const float4*>(ksrc);
            uint4 ku = { f2tf32(kv.x), f2tf32(kv.y), f2tf32(kv.z), f2tf32(kv.w) };
            *reinterpret_cast<uint4*>(Kc + row * AKP + c4 * 4) = ku;
            const float* vsrc = g_vt + (tokbase + jc + row) * DMODEL + h * HD + c4 * 4;
            float4 vv = *reinterpret_cast<const float4*>(vsrc);
            uint4 vu = { f2tf32(vv.x), f2tf32(vv.y), f2tf32(vv.z), f2tf32(vv.w) };
            *reinterpret_cast<uint4*>(Vc + row * AKP + c4 * 4) = vu;
        }
        if (tid < 64) Kc[tid * AKP + 64] = __float_as_uint(g_kt[bh * SEQ + jc + tid]);
        __syncthreads();

        // ---- S = Q @ K^T (m16 x n64, k=64) ----
        float sacc[8][4];
#pragma unroll
        for (int nt = 0; nt < 8; nt++)
#pragma unroll
            for (int c = 0; c < 4; c++) sacc[nt][c] = 0.f;
#pragma unroll
        for (int ks = 0; ks < 8; ks++) {
            int kb = ks * 8 + fk;
            uint32_t a0 = Qs[rowA * AKP + kb];
            uint32_t a1 = Qs[rowB * AKP + kb];
            uint32_t a2 = Qs[rowA * AKP + kb + 4];
            uint32_t a3 = Qs[rowB * AKP + kb + 4];
#pragma unroll
            for (int nt = 0; nt < 8; nt++) {
                uint32_t b0 = Kc[(nt * 8 + frow) * AKP + kb];
                uint32_t b1 = Kc[(nt * 8 + frow) * AKP + kb + 4];
                mma_tf32(sacc[nt], a0, a1, a2, a3, b0, b1);
            }
        }

        // ---- transform + store P ----
#pragma unroll
        for (int nt = 0; nt < 8; nt++) {
            int jb = nt * 8 + 2 * fk;
            float kt0 = __uint_as_float(Kc[jb * AKP + 64]);
            float kt1 = __uint_as_float(Kc[(jb + 1) * AKP + 64]);
            float e0 = pair_e(sacc[nt][0], kt0, qtA, cOQA, isA, BvA, tau, lam);
            float e1 = pair_e(sacc[nt][1], kt1, qtA, cOQA, isA, BvA, tau, lam);
            float e2 = pair_e(sacc[nt][2], kt0, qtB, cOQB, isB, BvB, tau, lam);
            float e3 = pair_e(sacc[nt][3], kt1, qtB, cOQB, isB, BvB, tau, lam);
            sumA += e0 + e1;
            sumB += e2 + e3;
            uint2 pA = { f2tf32(e0), f2tf32(e1) };
            *reinterpret_cast<uint2*>(Pc + rowA * AKP + jb) = pA;
            uint2 pB = { f2tf32(e2), f2tf32(e3) };
            *reinterpret_cast<uint2*>(Pc + rowB * AKP + jb) = pB;
        }
        __syncwarp();   // P rows of this warp read only by this warp

        // ---- O += P @ V (m16 x n64, k=64) ----
#pragma unroll
        for (int ks = 0; ks < 8; ks++) {
            int kb = ks * 8 + fk;
            uint32_t a0 = Pc[rowA * AKP + kb];
            uint32_t a1 = Pc[rowB * AKP + kb];
            uint32_t a2 = Pc[rowA * AKP + kb + 4];
            uint32_t a3 = Pc[rowB * AKP + kb + 4];
#pragma unroll
            for (int nt = 0; nt < 8; nt++) {
                uint32_t b0 = Vc[kb * AKP + nt * 8 + frow];
                uint32_t b1 = Vc[(kb + 4) * AKP + nt * 8 + frow];
                mma_tf32(Oacc[nt], a0, a1, a2, a3, b0, b1);
            }
        }
    }

    // ---- epilogue: row sums, normalize, expmap0, write ----
    sumA += __shfl_xor_sync(0xffffffffu, sumA, 1);
    sumA += __shfl_xor_sync(0xffffffffu, sumA, 2);
    sumB += __shfl_xor_sync(0xffffffffu, sumB, 1);
    sumB += __shfl_xor_sync(0xffffffffu, sumB, 2);
    float invA = 1.f / sumA, invB = 1.f / sumB;

    float aa[8][4];
    float n2A = 0.f, n2B = 0.f;
#pragma unroll
    for (int nt = 0; nt < 8; nt++) {
        aa[nt][0] = Oacc[nt][0] * invA;
        aa[nt][1] = Oacc[nt][1] * invA;
        aa[nt][2] = Oacc[nt][2] * invB;
        aa[nt][3] = Oacc[nt][3] * invB;
        n2A += aa[nt][0] * aa[nt][0] + aa[nt][1] * aa[nt][1];
        n2B += aa[nt][2] * aa[nt][2] + aa[nt][3] * aa[nt][3];
    }
    n2A += __shfl_xor_sync(0xffffffffu, n2A, 1);
    n2A += __shfl_xor_sync(0xffffffffu, n2A, 2);
    n2B += __shfl_xor_sync(0xffffffffu, n2B, 1);
    n2B += __shfl_xor_sync(0xffffffffu, n2B, 2);

    float nnA = sqrtf(n2A), nnB = sqrtf(n2B);
    float ttA = coshf(nnA), ttB = coshf(nnB);
    float sfA = sinhf(nnA) / fmaxf(nnA, 1e-8f);
    float sfB = sinhf(nnB) / fmaxf(nnB, 1e-8f);

    float* oA = g_attncat + (tokbase + i0 + rowA) * LDX + 1 + h * HD;
    float* oB = g_attncat + (tokbase + i0 + rowB) * LDX + 1 + h * HD;
#pragma unroll
    for (int nt = 0; nt < 8; nt++) {
        int col = nt * 8 + 2 * fk;
        oA[col]     = aa[nt][0] * sfA;
        oA[col + 1] = aa[nt][1] * sfA;
        oB[col]     = aa[nt][2] * sfB;
        oB[col + 1] = aa[nt][3] * sfB;
    }
    if (fk == 0) {
        g_attnt[(tokbase + i0 + rowA) * NHEAD + h] = ttA;
        g_attnt[(tokbase + i0 + rowB) * NHEAD + h] = ttB;
    }
}

// ---------------- t_new = sqrt(sum_h t_h^2 - 11) ---------------------------
__global__ void attn_time_kernel() {
    int t = blockIdx.x * 256 + threadIdx.x;
    if (t < TOK) {
        float s = 0.f;
#pragma unroll
        for (int hh = 0; hh < NHEAD; hh++) { float a = g_attnt[t * NHEAD + hh]; s += a * a; }
        g_attncat[t * LDX] = sqrtf(s - (float)(NHEAD - 1));
    }
}

// ---------------- residual: res = So + x_s ---------------------------------
__global__ void resid_kernel(const float* __restrict__ x) {
    int idx = blockIdx.x * 256 + threadIdx.x;
    if (idx < TOK * DMODEL) {
        int row = idx / DMODEL, c = idx % DMODEL;
        g_res[idx] = g_Sq[idx] + x[row * LDX + 1 + c];
    }
}

// ---------------- GELU (exact) + add_time over 3072 ------------------------
__global__ __launch_bounds__(256) void gelu_time_kernel() {
    int row = blockIdx.x;
    __shared__ float red[8];
    float ss = 0.f;
    for (int c = threadIdx.x; c < MLP; c += 256) {
        float v = g_Sm[row * MLP + c];
        float ge = 0.5f * v * (1.f + erff(v * 0.70710678118654752f));
        g_h3[row * (MLP + 1) + 1 + c] = ge;
        ss += ge * ge;
    }
    ss = block_sum(ss, red);
    if (threadIdx.x == 0) g_h3[row * (MLP + 1)] = sqrtf(1.f + ss);
}

// ---------------- final: out = add_time(Sm2 + res) -------------------------
__global__ __launch_bounds__(256) void final_kernel(float* __restrict__ out) {
    int row = blockIdx.x;
    __shared__ float red[8];
    float vals[3]; float ss = 0.f;
#pragma unroll
    for (int r = 0; r < 3; r++) {
        int c = threadIdx.x + r * 256;
        float f = g_Sk[row * DMODEL + c] + g_res[row * DMODEL + c];
        vals[r] = f; ss += f * f;
    }
    ss = block_sum(ss, red);
#pragma unroll
    for (int r = 0; r < 3; r++) {
        int c = threadIdx.x + r * 256;
        out[row * LDX + 1 + c] = vals[r];
    }
    if (threadIdx.x == 0) out[row * LDX] = sqrtf(1.f + ss);
}

// ---------------- host -----------------------------------------------------
extern "C" void kernel_launch(void* const* d_in, const int* in_sizes, int n_in,
                              void* d_out, int out_size)
{
    const float* x     = (const float*)d_in[0];
    const float* Wq    = (const float*)d_in[1];
    const float* Wk    = (const float*)d_in[2];
    const float* Wv    = (const float*)d_in[3];
    const float* Wo    = (const float*)d_in[4];
    const float* g1    = (const float*)d_in[5];
    const float* b1    = (const float*)d_in[6];
    const float* g2    = (const float*)d_in[7];
    const float* b2    = (const float*)d_in[8];
    const float* Wm1   = (const float*)d_in[9];
    const float* Wm2   = (const float*)d_in[10];
    const float* alpha = (const float*)d_in[11];
    const float* tau   = (const float*)d_in[12];
    const float* lam   = (const float*)d_in[13];
    float* out = (float*)d_out;

    const int ATTN_SMEM = 4 * ATILE * 4;     // 73728 B
    const int GEMM_SMEM = 4 * TILEU * 4;
    cudaFuncSetAttribute(attn_kernel, cudaFuncAttributeMaxDynamicSharedMemorySize, ATTN_SMEM);
    cudaFuncSetAttribute(gemm_tf32_kernel, cudaFuncAttributeMaxDynamicSharedMemorySize, GEMM_SMEM);
    cudaFuncSetAttribute(gemm_tf32_qkv_kernel, cudaFuncAttributeMaxDynamicSharedMemorySize, GEMM_SMEM);

    void *ah0, *aSq, *aSk, *aSv, *aSm, *acat, *ah2, *ah3, *ares;
    cudaGetSymbolAddress(&ah0,  g_h0);
    cudaGetSymbolAddress(&aSq,  g_Sq);
    cudaGetSymbolAddress(&aSk,  g_Sk);
    cudaGetSymbolAddress(&aSv,  g_Sv);
    cudaGetSymbolAddress(&aSm,  g_Sm);
    cudaGetSymbolAddress(&acat, g_attncat);
    cudaGetSymbolAddress(&ah2,  g_h2);
    cudaGetSymbolAddress(&ah3,  g_h3);
    cudaGetSymbolAddress(&ares, g_res);

    // 1. LN1
    ln_rows_kernel<<<TOK, 256>>>(x, LDX, 1, g1, b1, (float*)ah0);

    // 2. QKV projections, one launch (z = q/k/v)
    dim3 gqkv(DMODEL / BN, TOK / BM, 3);
    gemm_tf32_qkv_kernel<<<gqkv, 256, GEMM_SMEM>>>(
        (const float*)ah0, Wq, Wk, Wv, (float*)aSq, (float*)aSk, (float*)aSv);

    // 3. q_t, k_t, v_tan
    qkv_post_kernel<<<NBH * SEQ, 64>>>();

    // 4. attention (tensor-core flash, 64 queries / CTA)
    dim3 gattn(SEQ / 64, NBH);
    attn_kernel<<<gattn, 128, ATTN_SMEM>>>(alpha, tau, lam);
    attn_time_kernel<<<(TOK + 255) / 256, 256>>>();

    // 5. output projection (So reuses g_Sq)
    dim3 g768(DMODEL / BN, TOK / BM);
    gemm_tf32_kernel<<<g768, 256, GEMM_SMEM>>>((const float*)acat, Wo, (float*)aSq, LDX, LDX, LDX, DMODEL);

    // 6. residual + LN2
    resid_kernel<<<(TOK * DMODEL + 255) / 256, 256>>>(x);
    ln_rows_kernel<<<TOK, 256>>>((const float*)ares, DMODEL, 0, g2, b2, (float*)ah2);

    // 7. MLP up + GELU + add_time
    dim3 gm1(MLP / BN, TOK / BM);
    gemm_tf32_kernel<<<gm1, 256, GEMM_SMEM>>>((const float*)ah2, Wm1, (float*)aSm, LDX, LDX, LDX, MLP);
    gelu_time_kernel<<<TOK, 256>>>();

    // 8. MLP down (Sm2 reuses g_Sk)
    gemm_tf32_kernel<<<g768, 256, GEMM_SMEM>>>((const float*)ah3, Wm2, (float*)aSk, MLP + 1, MLP + 1, MLP + 1, DMODEL);

    // 9. final residual + add_time
    final_kernel<<<TOK, 256>>>(out);
}